// round 1
// baseline (speedup 1.0000x reference)
#include <cuda_runtime.h>

#define NPTS   200000
#define NREL   128
#define CHUNKS 12          // CTAs per relation in the main kernel
#define WPC    4           // warps per CTA (128 threads)

// ---- device scratch (no allocations allowed) ----
__device__ int g_counts[NREL];
__device__ int g_offsets[NREL + 1];
__device__ int g_cursor[NREL];
__device__ int g_pids[NPTS];

// Reset bin counters (must run every launch: graph replays).
__global__ void k_reset() {
    if (threadIdx.x < NREL) g_counts[threadIdx.x] = 0;
}

// Smem-aggregated histogram of rel[].
__global__ void k_hist(const int* __restrict__ rel, int n) {
    __shared__ int h[NREL];
    for (int i = threadIdx.x; i < NREL; i += blockDim.x) h[i] = 0;
    __syncthreads();
    for (int i = blockIdx.x * blockDim.x + threadIdx.x; i < n;
         i += gridDim.x * blockDim.x)
        atomicAdd(&h[rel[i]], 1);
    __syncthreads();
    for (int i = threadIdx.x; i < NREL; i += blockDim.x) {
        int v = h[i];
        if (v) atomicAdd(&g_counts[i], v);
    }
}

// Exclusive scan over 128 bins (single block, Hillis-Steele).
__global__ void k_scan() {
    __shared__ int s[NREL];
    int t = threadIdx.x;
    int c = g_counts[t];
    s[t] = c;
    __syncthreads();
#pragma unroll
    for (int d = 1; d < NREL; d <<= 1) {
        int v = (t >= d) ? s[t - d] : 0;
        __syncthreads();
        s[t] += v;
        __syncthreads();
    }
    int excl = s[t] - c;
    g_offsets[t] = excl;
    g_cursor[t]  = excl;
    if (t == NREL - 1) g_offsets[NREL] = s[t];
}

// Scatter point ids into per-relation lists. Order within a bin is
// non-deterministic but irrelevant: points are processed independently.
__global__ void k_scatter(const int* __restrict__ rel, int n) {
    int i = blockIdx.x * blockDim.x + threadIdx.x;
    if (i < n) {
        int r = rel[i];
        int pos = atomicAdd(&g_cursor[r], 1);
        g_pids[pos] = i;
    }
}

// Main: CTA = (relation r, chunk). Each lane owns one (block b, out-half h):
//   lane = 2*b + h,  b in [0,16), h in {0,1}
// and keeps its 32 weight floats (8 float4s: W[r][b][i][4h..4h+3], i=0..7)
// in REGISTERS for the whole CTA. Per point: 512B x read + 512B out write.
__global__ void __launch_bounds__(32 * WPC)
k_main(const float4* __restrict__ x4,
       const float4* __restrict__ w4,
       float4* __restrict__ out4) {
    int r     = blockIdx.x / CHUNKS;
    int chunk = blockIdx.x % CHUNKS;
    int lane  = threadIdx.x & 31;
    int wrp   = threadIdx.x >> 5;
    int b     = lane >> 1;
    int h     = lane & 1;

    // W element (r,b,i,o) at ((r*16+b)*8+i)*8+o ; as float4: (...)*2 + (o>>2)
    const float4* wp = w4 + (size_t)((r * 16 + b) * 8) * 2 + h;
    float4 wt[8];
#pragma unroll
    for (int i = 0; i < 8; i++) wt[i] = __ldg(wp + 2 * i);

    int begin = g_offsets[r];
    int end   = g_offsets[r + 1];
    const int stride = CHUNKS * WPC;

    for (int li = begin + chunk * WPC + wrp; li < end; li += stride) {
        int p = g_pids[li];
        const float4* xr = x4 + (size_t)p * 32;
        // features b*8 .. b*8+7 : float4 indices 2b and 2b+1
        float4 xa = __ldg(xr + 2 * b);
        float4 xb = __ldg(xr + 2 * b + 1);
        float xs[8] = {xa.x, xa.y, xa.z, xa.w, xb.x, xb.y, xb.z, xb.w};

        float a0 = 0.f, a1 = 0.f, a2 = 0.f, a3 = 0.f;
#pragma unroll
        for (int i = 0; i < 8; i++) {
            a0 = fmaf(xs[i], wt[i].x, a0);
            a1 = fmaf(xs[i], wt[i].y, a1);
            a2 = fmaf(xs[i], wt[i].z, a2);
            a3 = fmaf(xs[i], wt[i].w, a3);
        }
        // out features b*8+4h .. +3 : float4 index p*32 + 2b + h = p*32 + lane
        out4[(size_t)p * 32 + lane] = make_float4(a0, a1, a2, a3);
    }
}

extern "C" void kernel_launch(void* const* d_in, const int* in_sizes, int n_in,
                              void* d_out, int out_size) {
    const float* x      = (const float*)d_in[0];   // [NPTS, 128] f32
    const float* blocks = (const float*)d_in[1];   // [128,16,8,8] f32
    const int*   rel    = (const int*)d_in[2];     // [NPTS] i32
    int n = in_sizes[2];
    if (n > NPTS) n = NPTS;  // scratch bound

    k_reset<<<1, 128>>>();
    k_hist<<<200, 256>>>(rel, n);
    k_scan<<<1, 128>>>();
    k_scatter<<<(n + 255) / 256, 256>>>(rel, n);
    k_main<<<NREL * CHUNKS, 32 * WPC>>>(
        (const float4*)x, (const float4*)blocks, (float4*)d_out);
}

// round 2
// speedup vs baseline: 1.8489x; 1.8489x over previous
#include <cuda_runtime.h>

#define NPTS    200000
#define NREL    128
#define CAP     4096       // per-relation slot capacity (mean 1562, sd 39)
#define CHUNKS  24         // CTAs per relation in the main kernel
#define WPC     4          // warps per CTA (128 threads)
#define SCT_PTS 2048       // points per scatter block

// ---- device scratch (no allocations allowed) ----
__device__ int g_counts[NREL];
__device__ int g_pids[NREL * CAP];
__device__ int g_ovf_count;
__device__ int g_ovf[NPTS];

// Reset counters (graph replays => must run every launch).
__global__ void k_reset() {
    if (threadIdx.x < NREL) g_counts[threadIdx.x] = 0;
    if (threadIdx.x == 0) g_ovf_count = 0;
}

// Block-aggregated scatter: smem-local binning, ONE global atomic per
// (bin, block) to reserve a range, then conflict-spread smem atomics for
// local positions. Order within a bin is irrelevant (points independent).
__global__ void __launch_bounds__(256)
k_scatter(const int* __restrict__ rel, int n) {
    __shared__ int s_rel[SCT_PTS];
    __shared__ int s_hist[NREL];
    __shared__ int s_base[NREL];

    int start = blockIdx.x * SCT_PTS;
    int cnt = n - start;
    if (cnt > SCT_PTS) cnt = SCT_PTS;
    if (cnt <= 0) return;

    for (int i = threadIdx.x; i < NREL; i += blockDim.x) s_hist[i] = 0;
    __syncthreads();

    for (int i = threadIdx.x; i < cnt; i += blockDim.x) {
        int r = __ldg(rel + start + i);
        s_rel[i] = r;
        atomicAdd(&s_hist[r], 1);
    }
    __syncthreads();

    for (int i = threadIdx.x; i < NREL; i += blockDim.x) {
        int c = s_hist[i];
        s_base[i] = c ? atomicAdd(&g_counts[i], c) : 0;
        s_hist[i] = 0;   // reuse as local cursor
    }
    __syncthreads();

    for (int i = threadIdx.x; i < cnt; i += blockDim.x) {
        int r = s_rel[i];
        int pos = s_base[r] + atomicAdd(&s_hist[r], 1);
        if (pos < CAP) {
            g_pids[r * CAP + pos] = start + i;
        } else {                      // statistically unreachable guard
            int o = atomicAdd(&g_ovf_count, 1);
            g_ovf[o] = start + i;
        }
    }
}

// Main: CTA = (relation r, chunk). lane = 2*b + h owns block b, out-half h;
// its 32 weight floats live in registers for the whole CTA.
// Per point: 512B coalesced x read + 512B coalesced out write.
// 2-stage software pipeline: prefetch (pid -> x row) for iteration i+1
// while computing/storing iteration i.
__global__ void __launch_bounds__(32 * WPC)
k_main(const float4* __restrict__ x4,
       const float4* __restrict__ w4,
       float4* __restrict__ out4) {
    int r     = blockIdx.x / CHUNKS;
    int chunk = blockIdx.x % CHUNKS;
    int lane  = threadIdx.x & 31;
    int wrp   = threadIdx.x >> 5;
    int b     = lane >> 1;
    int h     = lane & 1;

    const float4* wp = w4 + (size_t)((r * 16 + b) * 8) * 2 + h;
    float4 wt[8];
#pragma unroll
    for (int i = 0; i < 8; i++) wt[i] = __ldg(wp + 2 * i);

    int cnt = g_counts[r];
    if (cnt > CAP) cnt = CAP;
    const int* pids = g_pids + r * CAP;
    const int stride = CHUNKS * WPC;

    int li = chunk * WPC + wrp;
    int p = 0;
    float4 xa, xb;
    if (li < cnt) {
        p  = __ldg(pids + li);
        xa = __ldg(x4 + (size_t)p * 32 + 2 * b);
        xb = __ldg(x4 + (size_t)p * 32 + 2 * b + 1);
    }

    while (li < cnt) {
        int li2 = li + stride;
        int p2 = 0;
        float4 xa2, xb2;
        if (li2 < cnt) {
            p2  = __ldg(pids + li2);
            xa2 = __ldg(x4 + (size_t)p2 * 32 + 2 * b);
            xb2 = __ldg(x4 + (size_t)p2 * 32 + 2 * b + 1);
        }

        float xs[8] = {xa.x, xa.y, xa.z, xa.w, xb.x, xb.y, xb.z, xb.w};
        float a0 = 0.f, a1 = 0.f, a2 = 0.f, a3 = 0.f;
#pragma unroll
        for (int i = 0; i < 8; i++) {
            a0 = fmaf(xs[i], wt[i].x, a0);
            a1 = fmaf(xs[i], wt[i].y, a1);
            a2 = fmaf(xs[i], wt[i].z, a2);
            a3 = fmaf(xs[i], wt[i].w, a3);
        }
        out4[(size_t)p * 32 + lane] = make_float4(a0, a1, a2, a3);

        li = li2; p = p2; xa = xa2; xb = xb2;
    }
}

// Overflow fallback: warp per point, direct weight gather. Normally
// g_ovf_count == 0 and this exits immediately.
__global__ void __launch_bounds__(128)
k_fallback(const float4* __restrict__ x4,
           const float4* __restrict__ w4,
           const int* __restrict__ rel,
           float4* __restrict__ out4) {
    int total = g_ovf_count;
    if (total == 0) return;
    int lane = threadIdx.x & 31;
    int wid  = (blockIdx.x * blockDim.x + threadIdx.x) >> 5;
    int nw   = (gridDim.x * blockDim.x) >> 5;
    int b = lane >> 1;
    int h = lane & 1;

    for (int idx = wid; idx < total; idx += nw) {
        int p = g_ovf[idx];
        int r = __ldg(rel + p);
        const float4* wp = w4 + (size_t)((r * 16 + b) * 8) * 2 + h;
        float4 xa = __ldg(x4 + (size_t)p * 32 + 2 * b);
        float4 xb = __ldg(x4 + (size_t)p * 32 + 2 * b + 1);
        float xs[8] = {xa.x, xa.y, xa.z, xa.w, xb.x, xb.y, xb.z, xb.w};
        float a0 = 0.f, a1 = 0.f, a2 = 0.f, a3 = 0.f;
#pragma unroll
        for (int i = 0; i < 8; i++) {
            float4 w = __ldg(wp + 2 * i);
            a0 = fmaf(xs[i], w.x, a0);
            a1 = fmaf(xs[i], w.y, a1);
            a2 = fmaf(xs[i], w.z, a2);
            a3 = fmaf(xs[i], w.w, a3);
        }
        out4[(size_t)p * 32 + lane] = make_float4(a0, a1, a2, a3);
    }
}

extern "C" void kernel_launch(void* const* d_in, const int* in_sizes, int n_in,
                              void* d_out, int out_size) {
    const float* x      = (const float*)d_in[0];   // [NPTS, 128] f32
    const float* blocks = (const float*)d_in[1];   // [128,16,8,8] f32
    const int*   rel    = (const int*)d_in[2];     // [NPTS] i32
    int n = in_sizes[2];
    if (n > NPTS) n = NPTS;  // scratch bound

    k_reset<<<1, 128>>>();
    k_scatter<<<(n + SCT_PTS - 1) / SCT_PTS, 256>>>(rel, n);
    k_main<<<NREL * CHUNKS, 32 * WPC>>>(
        (const float4*)x, (const float4*)blocks, (float4*)d_out);
    k_fallback<<<32, 128>>>(
        (const float4*)x, (const float4*)blocks, rel, (float4*)d_out);
}